// round 1
// baseline (speedup 1.0000x reference)
#include <cuda_runtime.h>
#include <math.h>

#define D      512
#define KNN    20
#define MAXN   100000
#define MAXCH  128
#define CHUNK  1024
#define FINF   3.0e38f

// ---------------- persistent scratch (no allocation allowed) ----------------
__device__ float g_tn2[MAXN];                 // ||t_n||^2
__device__ float g_score[MAXN];               // pass1 ordering score
__device__ float g_sq[KNN * MAXN];            // pass2 scores (8 MB)
__device__ float g_cand_d[KNN * MAXCH * KNN]; // stage-A candidates (values)
__device__ int   g_cand_i[KNN * MAXCH * KNN]; // stage-A candidates (indices)
__device__ int   g_knn_idx[KNN];              // pass1 top-20 indices
__device__ float g_nb[KNN * D];               // gathered neighbor rows
__device__ float g_pxk[KNN];                  // per-neighbor ||nb-X||^2
__device__ int   g_idx2[KNN * KNN];           // pass2 top-20 per neighbor
__device__ float g_sqnn[KNN * KNN];           // ||nn - nb||^2

// ---------------- f32x2 packed helpers ----------------
static __device__ __forceinline__ void fma2(unsigned long long& acc,
                                            unsigned long long a,
                                            unsigned long long b) {
    asm("fma.rn.f32x2 %0, %1, %2, %0;" : "+l"(acc) : "l"(a), "l"(b));
}
static __device__ __forceinline__ unsigned long long f2u(float a, float b) {
    unsigned long long u;
    asm("mov.b64 %0, {%1, %2};" : "=l"(u) : "f"(a), "f"(b));
    return u;
}
static __device__ __forceinline__ float2 u2f(unsigned long long u) {
    float2 f;
    asm("mov.b64 {%0, %1}, %2;" : "=f"(f.x), "=f"(f.y) : "l"(u));
    return f;
}

// ---------------- pass 1: tn2 and score = tn2 - 2*dot(X,t) ----------------
__global__ void k_pass1(const float* __restrict__ X, const float* __restrict__ T, int n) {
    int w    = blockIdx.x * (blockDim.x >> 5) + (threadIdx.x >> 5);
    int lane = threadIdx.x & 31;
    if (w >= n) return;
    const float4* row = (const float4*)(T + (size_t)w * D);
    const float4* xv  = (const float4*)X;
    float tn2 = 0.f, dx = 0.f;
#pragma unroll
    for (int i = 0; i < 4; i++) {
        float4 t = row[lane + 32 * i];
        float4 x = __ldg(&xv[lane + 32 * i]);
        tn2 += t.x * t.x + t.y * t.y + t.z * t.z + t.w * t.w;
        dx  += t.x * x.x + t.y * x.y + t.z * x.z + t.w * x.w;
    }
#pragma unroll
    for (int o = 16; o; o >>= 1) {
        tn2 += __shfl_xor_sync(0xffffffffu, tn2, o);
        dx  += __shfl_xor_sync(0xffffffffu, dx, o);
    }
    if (lane == 0) { g_tn2[w] = tn2; g_score[w] = tn2 - 2.f * dx; }
}

// ---------------- top-k stage A: top-20 per 1024-chunk ----------------
__global__ void k_topk_a(int src, int n) {
    int row = blockIdx.y, c = blockIdx.x;
    __shared__ float sv[CHUNK];
    __shared__ float wv[8];
    __shared__ int   wj[8];
    const float* v = (src == 0) ? g_score : (g_sq + (size_t)row * n);
    int base = c * CHUNK;
    for (int j = threadIdx.x; j < CHUNK; j += 256) {
        int g = base + j;
        sv[j] = (g < n) ? v[g] : FINF;
    }
    __syncthreads();
    float* od = g_cand_d + ((size_t)row * MAXCH + c) * KNN;
    int*   oi = g_cand_i + ((size_t)row * MAXCH + c) * KNN;
    for (int it = 0; it < KNN; it++) {
        float bv = FINF; int bj = CHUNK;
        for (int j = threadIdx.x; j < CHUNK; j += 256) {
            float x = sv[j];
            if (x < bv || (x == bv && j < bj)) { bv = x; bj = j; }
        }
#pragma unroll
        for (int o = 16; o; o >>= 1) {
            float ov = __shfl_xor_sync(0xffffffffu, bv, o);
            int   oj = __shfl_xor_sync(0xffffffffu, bj, o);
            if (ov < bv || (ov == bv && oj < bj)) { bv = ov; bj = oj; }
        }
        if ((threadIdx.x & 31) == 0) { wv[threadIdx.x >> 5] = bv; wj[threadIdx.x >> 5] = bj; }
        __syncthreads();
        if (threadIdx.x == 0) {
            for (int q = 1; q < 8; q++)
                if (wv[q] < bv || (wv[q] == bv && wj[q] < bj)) { bv = wv[q]; bj = wj[q]; }
            od[it] = bv; oi[it] = base + bj;
            if (bj < CHUNK) sv[bj] = FINF;
        }
        __syncthreads();
    }
}

// ---------------- top-k stage B: merge chunk candidates ----------------
__global__ void k_topk_b(int nchunks, int mode) {
    int row = blockIdx.x;
    int m = nchunks * KNN;
    __shared__ float sv[2048];
    __shared__ int   si[2048];
    __shared__ float wv[8];
    __shared__ int   wi[8], wj[8];
    const float* cd = g_cand_d + (size_t)row * MAXCH * KNN;
    const int*   ci = g_cand_i + (size_t)row * MAXCH * KNN;
    for (int j = threadIdx.x; j < 2048; j += 256) {
        if (j < m) { sv[j] = cd[j]; si[j] = ci[j]; }
        else       { sv[j] = FINF;  si[j] = 0x7fffffff; }
    }
    __syncthreads();
    for (int it = 0; it < KNN; it++) {
        float bv = FINF; int bi = 0x7fffffff; int bj = 0;
        for (int j = threadIdx.x; j < 2048; j += 256) {
            float x = sv[j]; int xi = si[j];
            if (x < bv || (x == bv && xi < bi)) { bv = x; bi = xi; bj = j; }
        }
#pragma unroll
        for (int o = 16; o; o >>= 1) {
            float ov = __shfl_xor_sync(0xffffffffu, bv, o);
            int   oi = __shfl_xor_sync(0xffffffffu, bi, o);
            int   oj = __shfl_xor_sync(0xffffffffu, bj, o);
            if (ov < bv || (ov == bv && oi < bi)) { bv = ov; bi = oi; bj = oj; }
        }
        int w = threadIdx.x >> 5;
        if ((threadIdx.x & 31) == 0) { wv[w] = bv; wi[w] = bi; wj[w] = bj; }
        __syncthreads();
        if (threadIdx.x == 0) {
            for (int q = 1; q < 8; q++)
                if (wv[q] < bv || (wv[q] == bv && wi[q] < bi)) { bv = wv[q]; bi = wi[q]; bj = wj[q]; }
            if (mode == 0) g_knn_idx[it] = bi;
            else           g_idx2[row * KNN + it] = bi;
            sv[bj] = FINF; si[bj] = 0x7fffffff;
        }
        __syncthreads();
    }
}

// ---------------- gather neighbor rows + ||nb - X||^2 ----------------
__global__ void k_gather(const float* __restrict__ X, const float* __restrict__ T) {
    int w = threadIdx.x >> 5, lane = threadIdx.x & 31;
    if (w >= KNN) return;
    int row = g_knn_idx[w];
    const float4* src = (const float4*)(T + (size_t)row * D);
    const float4* xv  = (const float4*)X;
    float px = 0.f;
#pragma unroll
    for (int i = 0; i < 4; i++) {
        float4 t = src[lane + 32 * i];
        float4 x = xv[lane + 32 * i];
        ((float4*)g_nb)[w * (D / 4) + lane + 32 * i] = t;
        float a = t.x - x.x, b = t.y - x.y, c = t.z - x.z, d = t.w - x.w;
        px += a * a + b * b + c * c + d * d;
    }
#pragma unroll
    for (int o = 16; o; o >>= 1) px += __shfl_xor_sync(0xffffffffu, px, o);
    if (lane == 0) g_pxk[w] = px;
}

// ---------------- pass 2: 20 dots per train point (f32x2 packed) ----------------
#define P2T 128   // threads/block
#define P2P 256   // points/block (2 per thread)
#define DC  32    // d-chunk
#define TST 17    // float2 row stride (32 data + 2 pad)
#define SMEM2 ((KNN * (D / 2) + P2P * TST) * 8)

__global__ __launch_bounds__(P2T) void k_pass2(const float* __restrict__ T, int n) {
    extern __shared__ unsigned long long sh[];
    unsigned long long* s_nb = sh;                   // [KNN][D/2]
    unsigned long long* s_t  = sh + KNN * (D / 2);   // [P2P][TST]

    const unsigned long long* nbsrc = (const unsigned long long*)g_nb;
    for (int i = threadIdx.x; i < KNN * (D / 2); i += P2T) s_nb[i] = nbsrc[i];

    int pbase = blockIdx.x * P2P;
    int l0 = threadIdx.x * 2, l1 = l0 + 1;

    unsigned long long a0[KNN], a1[KNN];
#pragma unroll
    for (int k = 0; k < KNN; k++) { a0[k] = 0ull; a1[k] = 0ull; }

    for (int c = 0; c < D / DC; c++) {
        __syncthreads();
#pragma unroll
        for (int r = 0; r < (P2P * (DC / 4)) / P2T; r++) {   // 16 float4 loads/thread
            int q  = threadIdx.x + r * P2T;
            int pt = q >> 3, fc = q & 7;
            int gp = pbase + pt;
            float4 v = make_float4(0.f, 0.f, 0.f, 0.f);
            if (gp < n) v = *(const float4*)(T + (size_t)gp * D + c * DC + fc * 4);
            s_t[pt * TST + fc * 2]     = f2u(v.x, v.y);
            s_t[pt * TST + fc * 2 + 1] = f2u(v.z, v.w);
        }
        __syncthreads();
#pragma unroll
        for (int dp = 0; dp < DC / 2; dp++) {
            unsigned long long t0 = s_t[l0 * TST + dp];
            unsigned long long t1 = s_t[l1 * TST + dp];
            int gdp = c * (DC / 2) + dp;
#pragma unroll
            for (int k = 0; k < KNN; k++) {
                unsigned long long nb = s_nb[k * (D / 2) + gdp];
                fma2(a0[k], t0, nb);
                fma2(a1[k], t1, nb);
            }
        }
    }

    int g0 = pbase + l0, g1 = pbase + l1;
    bool v0 = g0 < n, v1 = g1 < n;
    float tn0 = v0 ? g_tn2[g0] : 0.f;
    float tn1 = v1 ? g_tn2[g1] : 0.f;
#pragma unroll
    for (int k = 0; k < KNN; k++) {
        float2 f0 = u2f(a0[k]);
        float2 f1 = u2f(a1[k]);
        if (v0) g_sq[(size_t)k * n + g0] = tn0 - 2.f * (f0.x + f0.y);
        if (v1) g_sq[(size_t)k * n + g1] = tn1 - 2.f * (f1.x + f1.y);
    }
}

// ---------------- ||nn_ij - nb_i||^2 (exact, gathered) ----------------
__global__ void k_sqnn(const float* __restrict__ T) {
    int i = blockIdx.x / KNN;
    int idx = g_idx2[blockIdx.x];
    float4 t  = ((const float4*)(T + (size_t)idx * D))[threadIdx.x];
    float4 nb = ((const float4*)g_nb)[i * (D / 4) + threadIdx.x];
    float a = t.x - nb.x, b = t.y - nb.y, c = t.z - nb.z, d = t.w - nb.w;
    float s = a * a + b * b + c * c + d * d;
#pragma unroll
    for (int o = 16; o; o >>= 1) s += __shfl_xor_sync(0xffffffffu, s, o);
    __shared__ float ws[4];
    if ((threadIdx.x & 31) == 0) ws[threadIdx.x >> 5] = s;
    __syncthreads();
    if (threadIdx.x == 0) g_sqnn[blockIdx.x] = ws[0] + ws[1] + ws[2] + ws[3];
}

// ---------------- final scalar ----------------
__global__ void k_final(float* out) {
    int lane = threadIdx.x;
    float norm = 0.f, px = 0.f;
    if (lane < KNN) {
        float s = 0.f;
#pragma unroll
        for (int j = 0; j < KNN; j++) s += g_sqnn[lane * KNN + j];
        norm = sqrtf(s / (float)KNN);
        px = g_pxk[lane];
    }
#pragma unroll
    for (int o = 16; o; o >>= 1) {
        norm += __shfl_xor_sync(0xffffffffu, norm, o);
        px   += __shfl_xor_sync(0xffffffffu, px, o);
    }
    if (lane == 0) {
        float pdx = sqrtf(px / (float)KNN);
        float lof = pdx / norm * (float)KNN - 1.f;
        float r = erff(lof * 0.7071067811865476f);
        out[0] = fmaxf(r, 0.f);
    }
}

// ---------------- launch ----------------
extern "C" void kernel_launch(void* const* d_in, const int* in_sizes, int n_in,
                              void* d_out, int out_size) {
    const float* A = (const float*)d_in[0];
    const float* B = (const float*)d_in[1];
    const float *X, *T;
    int n;
    if (in_sizes[0] == D) { X = A; T = B; n = in_sizes[1] / D; }
    else                  { X = B; T = A; n = in_sizes[0] / D; }
    if (n > MAXN) n = MAXN;

    int nch = (n + CHUNK - 1) / CHUNK;

    cudaFuncSetAttribute(k_pass2, cudaFuncAttributeMaxDynamicSharedMemorySize, SMEM2);

    k_pass1<<<(n + 7) / 8, 256>>>(X, T, n);
    k_topk_a<<<dim3(nch, 1), 256>>>(0, n);
    k_topk_b<<<1, 256>>>(nch, 0);
    k_gather<<<1, 640>>>(X, T);
    k_pass2<<<(n + P2P - 1) / P2P, P2T, SMEM2>>>(T, n);
    k_topk_a<<<dim3(nch, KNN), 256>>>(1, n);
    k_topk_b<<<KNN, 256>>>(nch, 1);
    k_sqnn<<<KNN * KNN, 128>>>(T);
    k_final<<<1, 32>>>((float*)d_out);
}

// round 3
// speedup vs baseline: 1.1020x; 1.1020x over previous
#include <cuda_runtime.h>
#include <math.h>

#define D      512
#define KNN    20
#define MAXN   100000
#define MAXCH  128
#define CHUNK  1024
#define FINF   3.0e38f

// ---------------- persistent scratch (no allocation allowed) ----------------
__device__ float g_tn2[MAXN];
__device__ float g_score[MAXN];
__device__ float g_sq[KNN * MAXN];
__device__ float g_cand_d[KNN * MAXCH * KNN];
__device__ int   g_cand_i[KNN * MAXCH * KNN];
__device__ int   g_knn_idx[KNN];
__device__ float g_nb[KNN * D];
__device__ float g_pxk[KNN];
__device__ int   g_idx2[KNN * KNN];
__device__ float g_sqnn[KNN * KNN];

// ---------------- f32x2 packed helpers ----------------
static __device__ __forceinline__ void fma2(unsigned long long& acc,
                                            unsigned long long a,
                                            unsigned long long b) {
    asm("fma.rn.f32x2 %0, %1, %2, %0;" : "+l"(acc) : "l"(a), "l"(b));
}
static __device__ __forceinline__ unsigned long long f2u(float a, float b) {
    unsigned long long u;
    asm("mov.b64 %0, {%1, %2};" : "=l"(u) : "f"(a), "f"(b));
    return u;
}
static __device__ __forceinline__ float2 u2f(unsigned long long u) {
    float2 f;
    asm("mov.b64 {%0, %1}, %2;" : "=f"(f.x), "=f"(f.y) : "l"(u));
    return f;
}

// ---------------- pass 1: tn2 and score = tn2 - 2*dot(X,t) ----------------
__global__ void k_pass1(const float* __restrict__ X, const float* __restrict__ T, int n) {
    int w    = blockIdx.x * (blockDim.x >> 5) + (threadIdx.x >> 5);
    int lane = threadIdx.x & 31;
    if (w >= n) return;
    const float4* row = (const float4*)(T + (size_t)w * D);
    const float4* xv  = (const float4*)X;
    float tn2 = 0.f, dx = 0.f;
#pragma unroll
    for (int i = 0; i < 4; i++) {
        float4 t = row[lane + 32 * i];
        float4 x = __ldg(&xv[lane + 32 * i]);
        tn2 += t.x * t.x + t.y * t.y + t.z * t.z + t.w * t.w;
        dx  += t.x * x.x + t.y * x.y + t.z * x.z + t.w * x.w;
    }
#pragma unroll
    for (int o = 16; o; o >>= 1) {
        tn2 += __shfl_xor_sync(0xffffffffu, tn2, o);
        dx  += __shfl_xor_sync(0xffffffffu, dx, o);
    }
    if (lane == 0) { g_tn2[w] = tn2; g_score[w] = tn2 - 2.f * dx; }
}

// ---------------- top-k stage A: top-20 per 1024-chunk ----------------
__global__ void k_topk_a(int src, int n) {
    int row = blockIdx.y, c = blockIdx.x;
    __shared__ float sv[CHUNK];
    __shared__ float wv[8];
    __shared__ int   wj[8];
    const float* v = (src == 0) ? g_score : (g_sq + (size_t)row * n);
    int base = c * CHUNK;
    int tid = threadIdx.x, lane = tid & 31, wid = tid >> 5;
    for (int j = tid; j < CHUNK; j += 256) {
        int g = base + j;
        sv[j] = (g < n) ? v[g] : FINF;
    }
    __syncthreads();
    float* od = g_cand_d + ((size_t)row * MAXCH + c) * KNN;
    int*   oi = g_cand_i + ((size_t)row * MAXCH + c) * KNN;
    for (int it = 0; it < KNN; it++) {
        float bv = FINF; int bj = CHUNK;
#pragma unroll
        for (int r = 0; r < CHUNK / 256; r++) {
            int j = tid + r * 256;
            float x = sv[j];
            if (x < bv || (x == bv && j < bj)) { bv = x; bj = j; }
        }
#pragma unroll
        for (int o = 16; o; o >>= 1) {
            float ov = __shfl_xor_sync(0xffffffffu, bv, o);
            int   oj = __shfl_xor_sync(0xffffffffu, bj, o);
            if (ov < bv || (ov == bv && oj < bj)) { bv = ov; bj = oj; }
        }
        if (lane == 0) { wv[wid] = bv; wj[wid] = bj; }
        __syncthreads();
        if (tid < 32) {
            float v2 = (lane < 8) ? wv[lane] : FINF;
            int   j2 = (lane < 8) ? wj[lane] : CHUNK;
#pragma unroll
            for (int o = 4; o; o >>= 1) {
                float ov = __shfl_xor_sync(0xffffffffu, v2, o);
                int   oj = __shfl_xor_sync(0xffffffffu, j2, o);
                if (ov < v2 || (ov == v2 && oj < j2)) { v2 = ov; j2 = oj; }
            }
            if (lane == 0) { od[it] = v2; oi[it] = base + j2; sv[j2] = FINF; }
        }
        __syncthreads();
    }
}

// ---------------- top-k stage B: merge chunk candidates ----------------
__global__ void k_topk_b(int nchunks, int mode) {
    int row = blockIdx.x;
    int m = nchunks * KNN;
    __shared__ float sv[2048];
    __shared__ int   si[2048];
    __shared__ float wv[8];
    __shared__ int   wi[8], wj[8];
    int tid = threadIdx.x, lane = tid & 31, wid = tid >> 5;
    const float* cd = g_cand_d + (size_t)row * MAXCH * KNN;
    const int*   ci = g_cand_i + (size_t)row * MAXCH * KNN;
    for (int j = tid; j < 2048; j += 256) {
        if (j < m) { sv[j] = cd[j]; si[j] = ci[j]; }
        else       { sv[j] = FINF;  si[j] = 0x7fffffff; }
    }
    __syncthreads();
    for (int it = 0; it < KNN; it++) {
        float bv = FINF; int bi = 0x7fffffff; int bj = 0;
#pragma unroll
        for (int r = 0; r < 8; r++) {
            int j = tid + r * 256;
            float x = sv[j]; int xi = si[j];
            if (x < bv || (x == bv && xi < bi)) { bv = x; bi = xi; bj = j; }
        }
#pragma unroll
        for (int o = 16; o; o >>= 1) {
            float ov = __shfl_xor_sync(0xffffffffu, bv, o);
            int   oi = __shfl_xor_sync(0xffffffffu, bi, o);
            int   oj = __shfl_xor_sync(0xffffffffu, bj, o);
            if (ov < bv || (ov == bv && oi < bi)) { bv = ov; bi = oi; bj = oj; }
        }
        if (lane == 0) { wv[wid] = bv; wi[wid] = bi; wj[wid] = bj; }
        __syncthreads();
        if (tid < 32) {
            float v2 = (lane < 8) ? wv[lane] : FINF;
            int   i2 = (lane < 8) ? wi[lane] : 0x7fffffff;
            int   j2 = (lane < 8) ? wj[lane] : 0;
#pragma unroll
            for (int o = 4; o; o >>= 1) {
                float ov = __shfl_xor_sync(0xffffffffu, v2, o);
                int   oi = __shfl_xor_sync(0xffffffffu, i2, o);
                int   oj = __shfl_xor_sync(0xffffffffu, j2, o);
                if (ov < v2 || (ov == v2 && oi < i2)) { v2 = ov; i2 = oi; j2 = oj; }
            }
            if (lane == 0) {
                if (mode == 0) g_knn_idx[it] = i2;
                else           g_idx2[row * KNN + it] = i2;
                sv[j2] = FINF; si[j2] = 0x7fffffff;
            }
        }
        __syncthreads();
    }
}

// ---------------- gather neighbor rows + ||nb - X||^2 (one block/neighbor) ----
__global__ void k_gather(const float* __restrict__ X, const float* __restrict__ T) {
    int i = blockIdx.x;
    int tid = threadIdx.x, lane = tid & 31, wid = tid >> 5;
    int row = g_knn_idx[i];
    float4 t = ((const float4*)(T + (size_t)row * D))[tid];
    float4 x = ((const float4*)X)[tid];
    ((float4*)g_nb)[i * (D / 4) + tid] = t;
    float a = t.x - x.x, b = t.y - x.y, c = t.z - x.z, d = t.w - x.w;
    float s = a * a + b * b + c * c + d * d;
#pragma unroll
    for (int o = 16; o; o >>= 1) s += __shfl_xor_sync(0xffffffffu, s, o);
    __shared__ float ws[4];
    if (lane == 0) ws[wid] = s;
    __syncthreads();
    if (tid == 0) g_pxk[i] = ws[0] + ws[1] + ws[2] + ws[3];
}

// ---------------- pass 2: 20 dots per train point, register double-buffered ----
#define P2T 128   // threads/block
#define P2P 256   // points/block (2 per thread)
#define DC  32    // floats per chunk per point
#define NCH (D / DC)
#define TST 17    // f32x2 row stride (16 data + 1 pad)
#define RPT 16    // float4 prefetch regs per thread  (P2P*DC/4/P2T)
#define SMEM2 ((KNN * (D / 2) + P2P * TST) * 8)

__global__ __launch_bounds__(P2T) void k_pass2(const float* __restrict__ T, int n) {
    extern __shared__ unsigned long long sh[];
    unsigned long long* s_nb = sh;                   // [KNN][D/2]
    unsigned long long* s_t  = sh + KNN * (D / 2);   // [P2P][TST]

    int tid = threadIdx.x;
    int pbase = blockIdx.x * P2P;
    int l0 = tid * 2, l1 = l0 + 1;

    // cooperative load of neighbor matrix
    const unsigned long long* nbsrc = (const unsigned long long*)g_nb;
    for (int i = tid; i < KNN * (D / 2); i += P2T) s_nb[i] = nbsrc[i];

    unsigned long long a0[KNN], a1[KNN];
#pragma unroll
    for (int k = 0; k < KNN; k++) { a0[k] = 0ull; a1[k] = 0ull; }

    // prefetch chunk 0 into registers
    float4 r[RPT];
#pragma unroll
    for (int rr = 0; rr < RPT; rr++) {
        int q = tid + rr * P2T;
        int pt = q >> 3, fc = q & 7;
        int gp = pbase + pt;
        r[rr] = (gp < n) ? *(const float4*)(T + (size_t)gp * D + fc * 4)
                         : make_float4(0.f, 0.f, 0.f, 0.f);
    }

#pragma unroll 1
    for (int c = 0; c < NCH; c++) {
        __syncthreads();   // previous compute done; safe to overwrite s_t
#pragma unroll
        for (int rr = 0; rr < RPT; rr++) {
            int q = tid + rr * P2T;
            int pt = q >> 3, fc = q & 7;
            s_t[pt * TST + fc * 2]     = f2u(r[rr].x, r[rr].y);
            s_t[pt * TST + fc * 2 + 1] = f2u(r[rr].z, r[rr].w);
        }
        __syncthreads();   // stores visible

        if (c + 1 < NCH) { // prefetch next chunk; latency hides under compute
#pragma unroll
            for (int rr = 0; rr < RPT; rr++) {
                int q = tid + rr * P2T;
                int pt = q >> 3, fc = q & 7;
                int gp = pbase + pt;
                r[rr] = (gp < n) ? *(const float4*)(T + (size_t)gp * D + (c + 1) * DC + fc * 4)
                                 : make_float4(0.f, 0.f, 0.f, 0.f);
            }
        }

#pragma unroll 2
        for (int dp = 0; dp < DC / 2; dp++) {
            unsigned long long t0 = s_t[l0 * TST + dp];
            unsigned long long t1 = s_t[l1 * TST + dp];
            const unsigned long long* nbp = s_nb + (c * (DC / 2) + dp);
#pragma unroll
            for (int k = 0; k < KNN; k++) {
                unsigned long long nb = nbp[k * (D / 2)];
                fma2(a0[k], t0, nb);
                fma2(a1[k], t1, nb);
            }
        }
    }

    int g0 = pbase + l0, g1 = pbase + l1;
    bool v0 = g0 < n, v1 = g1 < n;
    float tn0 = v0 ? g_tn2[g0] : 0.f;
    float tn1 = v1 ? g_tn2[g1] : 0.f;
#pragma unroll
    for (int k = 0; k < KNN; k++) {
        float2 f0 = u2f(a0[k]);
        float2 f1 = u2f(a1[k]);
        if (v0) g_sq[(size_t)k * n + g0] = tn0 - 2.f * (f0.x + f0.y);
        if (v1) g_sq[(size_t)k * n + g1] = tn1 - 2.f * (f1.x + f1.y);
    }
}

// ---------------- ||nn_ij - nb_i||^2 (exact, gathered) ----------------
__global__ void k_sqnn(const float* __restrict__ T) {
    int i = blockIdx.x / KNN;
    int idx = g_idx2[blockIdx.x];
    float4 t  = ((const float4*)(T + (size_t)idx * D))[threadIdx.x];
    float4 nb = ((const float4*)g_nb)[i * (D / 4) + threadIdx.x];
    float a = t.x - nb.x, b = t.y - nb.y, c = t.z - nb.z, d = t.w - nb.w;
    float s = a * a + b * b + c * c + d * d;
#pragma unroll
    for (int o = 16; o; o >>= 1) s += __shfl_xor_sync(0xffffffffu, s, o);
    __shared__ float ws[4];
    if ((threadIdx.x & 31) == 0) ws[threadIdx.x >> 5] = s;
    __syncthreads();
    if (threadIdx.x == 0) g_sqnn[blockIdx.x] = ws[0] + ws[1] + ws[2] + ws[3];
}

// ---------------- final scalar ----------------
__global__ void k_final(float* out) {
    int lane = threadIdx.x;
    float norm = 0.f, px = 0.f;
    if (lane < KNN) {
        float s = 0.f;
#pragma unroll
        for (int j = 0; j < KNN; j++) s += g_sqnn[lane * KNN + j];
        norm = sqrtf(s / (float)KNN);
        px = g_pxk[lane];
    }
#pragma unroll
    for (int o = 16; o; o >>= 1) {
        norm += __shfl_xor_sync(0xffffffffu, norm, o);
        px   += __shfl_xor_sync(0xffffffffu, px, o);
    }
    if (lane == 0) {
        float pdx = sqrtf(px / (float)KNN);
        float lof = pdx / norm * (float)KNN - 1.f;
        float r = erff(lof * 0.7071067811865476f);
        out[0] = fmaxf(r, 0.f);
    }
}

// ---------------- launch ----------------
extern "C" void kernel_launch(void* const* d_in, const int* in_sizes, int n_in,
                              void* d_out, int out_size) {
    const float* A = (const float*)d_in[0];
    const float* B = (const float*)d_in[1];
    const float *X, *T;
    int n;
    if (in_sizes[0] == D) { X = A; T = B; n = in_sizes[1] / D; }
    else                  { X = B; T = A; n = in_sizes[0] / D; }
    if (n > MAXN) n = MAXN;

    int nch = (n + CHUNK - 1) / CHUNK;

    cudaFuncSetAttribute(k_pass2, cudaFuncAttributeMaxDynamicSharedMemorySize, SMEM2);

    k_pass1<<<(n + 7) / 8, 256>>>(X, T, n);
    k_topk_a<<<dim3(nch, 1), 256>>>(0, n);
    k_topk_b<<<1, 256>>>(nch, 0);
    k_gather<<<KNN, 128>>>(X, T);
    k_pass2<<<(n + P2P - 1) / P2P, P2T, SMEM2>>>(T, n);
    k_topk_a<<<dim3(nch, KNN), 256>>>(1, n);
    k_topk_b<<<KNN, 256>>>(nch, 1);
    k_sqnn<<<KNN * KNN, 128>>>(T);
    k_final<<<1, 32>>>((float*)d_out);
}

// round 4
// speedup vs baseline: 1.2143x; 1.1019x over previous
#include <cuda_runtime.h>
#include <math.h>

#define D      512
#define KNN    20
#define MAXN   100000
#define MAXCH  128
#define CHUNK  1024
#define FINF   3.0e38f

// ---------------- persistent scratch ----------------
__device__ float g_tn2[MAXN];
__device__ float g_score[MAXN];
__device__ float g_sq[KNN * MAXN];
__device__ float g_cand_d[KNN * MAXCH * KNN];
__device__ int   g_cand_i[KNN * MAXCH * KNN];
__device__ float g_nb[KNN * D];
__device__ float g_pxk[KNN];
__device__ float g_sqnn[KNN * KNN];

// ---------------- f32x2 packed helpers ----------------
static __device__ __forceinline__ void fma2(unsigned long long& acc,
                                            unsigned long long a,
                                            unsigned long long b) {
    asm("fma.rn.f32x2 %0, %1, %2, %0;" : "+l"(acc) : "l"(a), "l"(b));
}
static __device__ __forceinline__ float2 u2f(unsigned long long u) {
    float2 f;
    asm("mov.b64 {%0, %1}, %2;" : "=f"(f.x), "=f"(f.y) : "l"(u));
    return f;
}

// ---------------- pass 1: tn2 and score = tn2 - 2*dot(X,t) ----------------
__global__ void k_pass1(const float* __restrict__ X, const float* __restrict__ T, int n) {
    int w    = blockIdx.x * (blockDim.x >> 5) + (threadIdx.x >> 5);
    int lane = threadIdx.x & 31;
    if (w >= n) return;
    const float4* row = (const float4*)(T + (size_t)w * D);
    const float4* xv  = (const float4*)X;
    float tn2 = 0.f, dx = 0.f;
#pragma unroll
    for (int i = 0; i < 4; i++) {
        float4 t = row[lane + 32 * i];
        float4 x = __ldg(&xv[lane + 32 * i]);
        tn2 += t.x * t.x + t.y * t.y + t.z * t.z + t.w * t.w;
        dx  += t.x * x.x + t.y * x.y + t.z * x.z + t.w * x.w;
    }
#pragma unroll
    for (int o = 16; o; o >>= 1) {
        tn2 += __shfl_xor_sync(0xffffffffu, tn2, o);
        dx  += __shfl_xor_sync(0xffffffffu, dx, o);
    }
    if (lane == 0) { g_tn2[w] = tn2; g_score[w] = tn2 - 2.f * dx; }
}

// ---------------- stage A: warp-per-chunk register top-20, no syncs ----------------
__global__ void k_topk_a(int src, int n, int nch) {
    int wg   = blockIdx.x * (blockDim.x >> 5) + (threadIdx.x >> 5);
    int lane = threadIdx.x & 31;
    int rows = src ? KNN : 1;
    if (wg >= rows * nch) return;
    int row = wg / nch, c = wg % nch;
    const float* v = src ? (g_sq + (size_t)row * n) : g_score;
    int base = c * CHUNK;

    float val[32];
#pragma unroll
    for (int r = 0; r < 32; r++) {
        int g = base + lane + 32 * r;
        val[r] = (g < n) ? v[g] : FINF;
    }
    float* od = g_cand_d + ((size_t)row * MAXCH + c) * KNN;
    int*   oi = g_cand_i + ((size_t)row * MAXCH + c) * KNN;
    int ibase = base + lane;

    for (int it = 0; it < KNN; it++) {
        float bv = val[0]; int br = 0;
#pragma unroll
        for (int r = 1; r < 32; r++)
            if (val[r] < bv) { bv = val[r]; br = r; }   // strict < keeps lowest r (lowest idx)
        int bi = (bv >= FINF) ? 0x7fffffff : (ibase + (br << 5));
#pragma unroll
        for (int o = 16; o; o >>= 1) {
            float ov = __shfl_xor_sync(0xffffffffu, bv, o);
            int   oj = __shfl_xor_sync(0xffffffffu, bi, o);
            if (ov < bv || (ov == bv && oj < bi)) { bv = ov; bi = oj; }
        }
        int rel = bi - ibase;       // == br<<5 only on the winning lane
#pragma unroll
        for (int r = 0; r < 32; r++)
            if (rel == (r << 5)) val[r] = FINF;
        if (lane == 0) { od[it] = bv; oi[it] = bi; }
    }
}

// ---------------- stage B: 2-phase warp-register merge, fused epilogues ----------------
__global__ void k_topk_b(int nchunks, int mode, const float* __restrict__ X,
                         const float* __restrict__ T, int n) {
    int row = blockIdx.x;
    int m = nchunks * KNN;
    int tid = threadIdx.x, lane = tid & 31, w = tid >> 5;
    __shared__ float s_cv[8 * KNN];
    __shared__ int   s_ci[8 * KNN];
    __shared__ int   s_fi[KNN];
    const float* cd = g_cand_d + (size_t)row * MAXCH * KNN;
    const int*   ci = g_cand_i + (size_t)row * MAXCH * KNN;

    // phase 1: warp top-20 of its 256-slice (registers, no sync)
    float val[8]; int idx[8];
#pragma unroll
    for (int r = 0; r < 8; r++) {
        int j = w * 256 + lane + 32 * r;
        bool ok = j < m;
        val[r] = ok ? cd[j] : FINF;
        idx[r] = ok ? ci[j] : 0x7fffffff;
    }
    for (int it = 0; it < KNN; it++) {
        float bv = val[0]; int bi = idx[0];
#pragma unroll
        for (int r = 1; r < 8; r++)
            if (val[r] < bv || (val[r] == bv && idx[r] < bi)) { bv = val[r]; bi = idx[r]; }
#pragma unroll
        for (int o = 16; o; o >>= 1) {
            float ov = __shfl_xor_sync(0xffffffffu, bv, o);
            int   oj = __shfl_xor_sync(0xffffffffu, bi, o);
            if (ov < bv || (ov == bv && oj < bi)) { bv = ov; bi = oj; }
        }
#pragma unroll
        for (int r = 0; r < 8; r++)
            if (idx[r] == bi) val[r] = FINF;
        if (lane == 0) { s_cv[w * KNN + it] = bv; s_ci[w * KNN + it] = bi; }
    }
    __syncthreads();

    // phase 2: warp 0 merges 160 candidates
    if (w == 0) {
        float v2[5]; int i2[5];
#pragma unroll
        for (int r = 0; r < 5; r++) { int j = lane + 32 * r; v2[r] = s_cv[j]; i2[r] = s_ci[j]; }
        for (int it = 0; it < KNN; it++) {
            float bv = v2[0]; int bi = i2[0];
#pragma unroll
            for (int r = 1; r < 5; r++)
                if (v2[r] < bv || (v2[r] == bv && i2[r] < bi)) { bv = v2[r]; bi = i2[r]; }
#pragma unroll
            for (int o = 16; o; o >>= 1) {
                float ov = __shfl_xor_sync(0xffffffffu, bv, o);
                int   oj = __shfl_xor_sync(0xffffffffu, bi, o);
                if (ov < bv || (ov == bv && oj < bi)) { bv = ov; bi = oj; }
            }
#pragma unroll
            for (int r = 0; r < 5; r++)
                if (i2[r] == bi) v2[r] = FINF;
            if (lane == 0) s_fi[it] = bi;
        }
    }
    __syncthreads();

    if (mode == 0) {
        // fused gather: warp w handles neighbors w, w+8, w+16
        for (int i = w; i < KNN; i += 8) {
            int rowi = s_fi[i];
            float px = 0.f;
#pragma unroll
            for (int q = 0; q < 4; q++) {
                float4 t = ((const float4*)(T + (size_t)rowi * D))[lane + 32 * q];
                float4 x = ((const float4*)X)[lane + 32 * q];
                ((float4*)g_nb)[i * (D / 4) + lane + 32 * q] = t;
                float a = t.x - x.x, b = t.y - x.y, cc = t.z - x.z, d = t.w - x.w;
                px += a * a + b * b + cc * cc + d * d;
            }
#pragma unroll
            for (int o = 16; o; o >>= 1) px += __shfl_xor_sync(0xffffffffu, px, o);
            if (lane == 0) g_pxk[i] = px;
        }
    } else {
        // fused sqnn: warp w handles nn j = w, w+8, w+16 of neighbor 'row'
        for (int j = w; j < KNN; j += 8) {
            int rowj = s_fi[j];
            float s = 0.f;
#pragma unroll
            for (int q = 0; q < 4; q++) {
                float4 t  = ((const float4*)(T + (size_t)rowj * D))[lane + 32 * q];
                float4 nb = ((const float4*)g_nb)[row * (D / 4) + lane + 32 * q];
                float a = t.x - nb.x, b = t.y - nb.y, cc = t.z - nb.z, d = t.w - nb.w;
                s += a * a + b * b + cc * cc + d * d;
            }
#pragma unroll
            for (int o = 16; o; o >>= 1) s += __shfl_xor_sync(0xffffffffu, s, o);
            if (lane == 0) g_sqnn[row * KNN + j] = s;
        }
    }
}

// ---------------- pass 2: cp.async 3-stage pipeline, LDS.128 compute ----------------
#define P2T   128                 // threads/block
#define P2P   256                 // points/block (2 per thread)
#define DCF   16                  // floats per chunk per point
#define NCH2  (D / DCF)           // 32 chunks
#define ROWB  80                  // padded bytes per point row (64 data + 16 pad)
#define NBSZ  (KNN * D * 4)       // 40960 bytes
#define BUFSZ (P2P * ROWB)        // 20480 bytes
#define SMEM2 (NBSZ + 3 * BUFSZ)  // 102400 bytes

static __device__ __forceinline__ void p2_issue(const float* __restrict__ T, int n,
                                                int pbase, int tid, char* dst, int c) {
#pragma unroll
    for (int rr = 0; rr < 8; rr++) {
        int q  = tid + rr * P2T;
        int pt = q >> 2, fc = q & 3;
        int gp = pbase + pt;
        int sz = (gp < n) ? 16 : 0;
        const float* src = T + (size_t)(gp < n ? gp : 0) * D + c * DCF + fc * 4;
        unsigned int d = (unsigned int)__cvta_generic_to_shared(dst + pt * ROWB + fc * 16);
        asm volatile("cp.async.cg.shared.global [%0], [%1], 16, %2;"
                     :: "r"(d), "l"(src), "r"(sz));
    }
    asm volatile("cp.async.commit_group;");
}

__global__ __launch_bounds__(P2T) void k_pass2(const float* __restrict__ T, int n) {
    extern __shared__ char sh[];
    const ulonglong2* s_nb = (const ulonglong2*)sh;      // [KNN][128] u128
    char* bufs = sh + NBSZ;

    int tid = threadIdx.x;
    int pbase = blockIdx.x * P2P;

    // kick off first 3 chunks
    p2_issue(T, n, pbase, tid, bufs + 0 * BUFSZ, 0);
    p2_issue(T, n, pbase, tid, bufs + 1 * BUFSZ, 1);
    p2_issue(T, n, pbase, tid, bufs + 2 * BUFSZ, 2);

    // cooperative load of neighbor matrix
    {
        const unsigned long long* nbsrc = (const unsigned long long*)g_nb;
        unsigned long long* nbdst = (unsigned long long*)sh;
        for (int i = tid; i < KNN * (D / 2); i += P2T) nbdst[i] = nbsrc[i];
    }

    unsigned long long a0[KNN], a1[KNN];
#pragma unroll
    for (int k = 0; k < KNN; k++) { a0[k] = 0ull; a1[k] = 0ull; }

    int bsel = 0;
#pragma unroll 1
    for (int c = 0; c < NCH2; c++) {
        if (c <= NCH2 - 3)      asm volatile("cp.async.wait_group 2;");
        else if (c == NCH2 - 2) asm volatile("cp.async.wait_group 1;");
        else                    asm volatile("cp.async.wait_group 0;");
        __syncthreads();

        const char* tb = bufs + bsel * BUFSZ;
        const ulonglong2* t0p = (const ulonglong2*)(tb + (2 * tid) * ROWB);
        const ulonglong2* t1p = (const ulonglong2*)(tb + (2 * tid + 1) * ROWB);
#pragma unroll
        for (int dq = 0; dq < DCF / 4; dq++) {
            ulonglong2 t0 = t0p[dq];
            ulonglong2 t1 = t1p[dq];
            int dqg = c * (DCF / 4) + dq;
#pragma unroll
            for (int k = 0; k < KNN; k++) {
                ulonglong2 nb = s_nb[k * (D / 4) + dqg];
                fma2(a0[k], t0.x, nb.x);
                fma2(a0[k], t0.y, nb.y);
                fma2(a1[k], t1.x, nb.x);
                fma2(a1[k], t1.y, nb.y);
            }
        }
        __syncthreads();
        if (c + 3 < NCH2) p2_issue(T, n, pbase, tid, bufs + bsel * BUFSZ, c + 3);
        bsel = (bsel == 2) ? 0 : bsel + 1;
    }

    int g0 = pbase + 2 * tid, g1 = g0 + 1;
    bool v0 = g0 < n, v1 = g1 < n;
    float tn0 = v0 ? g_tn2[g0] : 0.f;
    float tn1 = v1 ? g_tn2[g1] : 0.f;
#pragma unroll
    for (int k = 0; k < KNN; k++) {
        float2 f0 = u2f(a0[k]);
        float2 f1 = u2f(a1[k]);
        if (v0) g_sq[(size_t)k * n + g0] = tn0 - 2.f * (f0.x + f0.y);
        if (v1) g_sq[(size_t)k * n + g1] = tn1 - 2.f * (f1.x + f1.y);
    }
}

// ---------------- final scalar ----------------
__global__ void k_final(float* out) {
    int lane = threadIdx.x;
    float norm = 0.f, px = 0.f;
    if (lane < KNN) {
        float s = 0.f;
#pragma unroll
        for (int j = 0; j < KNN; j++) s += g_sqnn[lane * KNN + j];
        norm = sqrtf(s / (float)KNN);
        px = g_pxk[lane];
    }
#pragma unroll
    for (int o = 16; o; o >>= 1) {
        norm += __shfl_xor_sync(0xffffffffu, norm, o);
        px   += __shfl_xor_sync(0xffffffffu, px, o);
    }
    if (lane == 0) {
        float pdx = sqrtf(px / (float)KNN);
        float lof = pdx / norm * (float)KNN - 1.f;
        float r = erff(lof * 0.7071067811865476f);
        out[0] = fmaxf(r, 0.f);
    }
}

// ---------------- launch ----------------
extern "C" void kernel_launch(void* const* d_in, const int* in_sizes, int n_in,
                              void* d_out, int out_size) {
    const float* A = (const float*)d_in[0];
    const float* B = (const float*)d_in[1];
    const float *X, *T;
    int n;
    if (in_sizes[0] == D) { X = A; T = B; n = in_sizes[1] / D; }
    else                  { X = B; T = A; n = in_sizes[0] / D; }
    if (n > MAXN) n = MAXN;

    int nch = (n + CHUNK - 1) / CHUNK;

    cudaFuncSetAttribute(k_pass2, cudaFuncAttributeMaxDynamicSharedMemorySize, SMEM2);

    k_pass1<<<(n + 7) / 8, 256>>>(X, T, n);
    k_topk_a<<<(nch + 7) / 8, 256>>>(0, n, nch);
    k_topk_b<<<1, 256>>>(nch, 0, X, T, n);
    k_pass2<<<(n + P2P - 1) / P2P, P2T, SMEM2>>>(T, n);
    k_topk_a<<<(nch * KNN + 7) / 8, 256>>>(1, n, nch);
    k_topk_b<<<KNN, 256>>>(nch, 1, X, T, n);
    k_final<<<1, 32>>>((float*)d_out);
}

// round 6
// speedup vs baseline: 1.3523x; 1.1136x over previous
#include <cuda_runtime.h>
#include <math.h>

#define D      512
#define KNN    20
#define MAXN   100000
#define MAXCH  128
#define CHUNK  1024
#define FINF   3.0e38f

// ---------------- persistent scratch ----------------
__device__ float g_tn2[MAXN];
__device__ float g_score[MAXN];
__device__ float g_sq[KNN * MAXN];
__device__ float g_cand_d[KNN * MAXCH * KNN];
__device__ int   g_cand_i[KNN * MAXCH * KNN];
__device__ float g_nb[KNN * D];
__device__ float g_pxk[KNN];
__device__ float g_sqnn[KNN * KNN];

// ---------------- f32x2 packed helpers ----------------
static __device__ __forceinline__ void fma2(unsigned long long& acc,
                                            unsigned long long a,
                                            unsigned long long b) {
    asm("fma.rn.f32x2 %0, %1, %2, %0;" : "+l"(acc) : "l"(a), "l"(b));
}
static __device__ __forceinline__ float2 u2f(unsigned long long u) {
    float2 f;
    asm("mov.b64 {%0, %1}, %2;" : "=f"(f.x), "=f"(f.y) : "l"(u));
    return f;
}

// ---------------- pass 1: tn2 and score = tn2 - 2*dot(X,t) ----------------
__global__ void k_pass1(const float* __restrict__ X, const float* __restrict__ T, int n) {
    int w    = blockIdx.x * (blockDim.x >> 5) + (threadIdx.x >> 5);
    int lane = threadIdx.x & 31;
    if (w >= n) return;
    const float4* row = (const float4*)(T + (size_t)w * D);
    const float4* xv  = (const float4*)X;
    float tn2 = 0.f, dx = 0.f;
#pragma unroll
    for (int i = 0; i < 4; i++) {
        float4 t = row[lane + 32 * i];
        float4 x = __ldg(&xv[lane + 32 * i]);
        tn2 += t.x * t.x + t.y * t.y + t.z * t.z + t.w * t.w;
        dx  += t.x * x.x + t.y * x.y + t.z * x.z + t.w * x.w;
    }
#pragma unroll
    for (int o = 16; o; o >>= 1) {
        tn2 += __shfl_xor_sync(0xffffffffu, tn2, o);
        dx  += __shfl_xor_sync(0xffffffffu, dx, o);
    }
    if (lane == 0) { g_tn2[w] = tn2; g_score[w] = tn2 - 2.f * dx; }
}

// ---------------- stage A: warp-per-chunk register top-20, no syncs ----------------
__global__ void k_topk_a(int src, int n, int nch) {
    int wg   = blockIdx.x * (blockDim.x >> 5) + (threadIdx.x >> 5);
    int lane = threadIdx.x & 31;
    int rows = src ? KNN : 1;
    if (wg >= rows * nch) return;
    int row = wg / nch, c = wg % nch;
    const float* v = src ? (g_sq + (size_t)row * n) : g_score;
    int base = c * CHUNK;

    float val[32];
#pragma unroll
    for (int r = 0; r < 32; r++) {
        int g = base + lane + 32 * r;
        val[r] = (g < n) ? v[g] : FINF;
    }
    float* od = g_cand_d + ((size_t)row * MAXCH + c) * KNN;
    int*   oi = g_cand_i + ((size_t)row * MAXCH + c) * KNN;
    int ibase = base + lane;

    for (int it = 0; it < KNN; it++) {
        float bv = val[0]; int br = 0;
#pragma unroll
        for (int r = 1; r < 32; r++)
            if (val[r] < bv) { bv = val[r]; br = r; }
        int bi = (bv >= FINF) ? 0x7fffffff : (ibase + (br << 5));
#pragma unroll
        for (int o = 16; o; o >>= 1) {
            float ov = __shfl_xor_sync(0xffffffffu, bv, o);
            int   oj = __shfl_xor_sync(0xffffffffu, bi, o);
            if (ov < bv || (ov == bv && oj < bi)) { bv = ov; bi = oj; }
        }
        int rel = bi - ibase;
#pragma unroll
        for (int r = 0; r < 32; r++)
            if (rel == (r << 5)) val[r] = FINF;
        if (lane == 0) { od[it] = bv; oi[it] = bi; }
    }
}

// ---------------- stage B: 2-phase warp-register merge, fused epilogues ----------------
__global__ void k_topk_b(int nchunks, int mode, const float* __restrict__ X,
                         const float* __restrict__ T, int n) {
    int row = blockIdx.x;
    int m = nchunks * KNN;
    int tid = threadIdx.x, lane = tid & 31, w = tid >> 5;
    __shared__ float s_cv[8 * KNN];
    __shared__ int   s_ci[8 * KNN];
    __shared__ int   s_fi[KNN];
    const float* cd = g_cand_d + (size_t)row * MAXCH * KNN;
    const int*   ci = g_cand_i + (size_t)row * MAXCH * KNN;

    float val[8]; int idx[8];
#pragma unroll
    for (int r = 0; r < 8; r++) {
        int j = w * 256 + lane + 32 * r;
        bool ok = j < m;
        val[r] = ok ? cd[j] : FINF;
        idx[r] = ok ? ci[j] : 0x7fffffff;
    }
    for (int it = 0; it < KNN; it++) {
        float bv = val[0]; int bi = idx[0];
#pragma unroll
        for (int r = 1; r < 8; r++)
            if (val[r] < bv || (val[r] == bv && idx[r] < bi)) { bv = val[r]; bi = idx[r]; }
#pragma unroll
        for (int o = 16; o; o >>= 1) {
            float ov = __shfl_xor_sync(0xffffffffu, bv, o);
            int   oj = __shfl_xor_sync(0xffffffffu, bi, o);
            if (ov < bv || (ov == bv && oj < bi)) { bv = ov; bi = oj; }
        }
#pragma unroll
        for (int r = 0; r < 8; r++)
            if (idx[r] == bi) val[r] = FINF;
        if (lane == 0) { s_cv[w * KNN + it] = bv; s_ci[w * KNN + it] = bi; }
    }
    __syncthreads();

    if (w == 0) {
        float v2[5]; int i2[5];
#pragma unroll
        for (int r = 0; r < 5; r++) { int j = lane + 32 * r; v2[r] = s_cv[j]; i2[r] = s_ci[j]; }
        for (int it = 0; it < KNN; it++) {
            float bv = v2[0]; int bi = i2[0];
#pragma unroll
            for (int r = 1; r < 5; r++)
                if (v2[r] < bv || (v2[r] == bv && i2[r] < bi)) { bv = v2[r]; bi = i2[r]; }
#pragma unroll
            for (int o = 16; o; o >>= 1) {
                float ov = __shfl_xor_sync(0xffffffffu, bv, o);
                int   oj = __shfl_xor_sync(0xffffffffu, bi, o);
                if (ov < bv || (ov == bv && oj < bi)) { bv = ov; bi = oj; }
            }
#pragma unroll
            for (int r = 0; r < 5; r++)
                if (i2[r] == bi) v2[r] = FINF;
            if (lane == 0) s_fi[it] = bi;
        }
    }
    __syncthreads();

    if (mode == 0) {
        for (int i = w; i < KNN; i += 8) {
            int rowi = s_fi[i];
            float px = 0.f;
#pragma unroll
            for (int q = 0; q < 4; q++) {
                float4 t = ((const float4*)(T + (size_t)rowi * D))[lane + 32 * q];
                float4 x = ((const float4*)X)[lane + 32 * q];
                ((float4*)g_nb)[i * (D / 4) + lane + 32 * q] = t;
                float a = t.x - x.x, b = t.y - x.y, cc = t.z - x.z, d = t.w - x.w;
                px += a * a + b * b + cc * cc + d * d;
            }
#pragma unroll
            for (int o = 16; o; o >>= 1) px += __shfl_xor_sync(0xffffffffu, px, o);
            if (lane == 0) g_pxk[i] = px;
        }
    } else {
        for (int j = w; j < KNN; j += 8) {
            int rowj = s_fi[j];
            float s = 0.f;
#pragma unroll
            for (int q = 0; q < 4; q++) {
                float4 t  = ((const float4*)(T + (size_t)rowj * D))[lane + 32 * q];
                float4 nb = ((const float4*)g_nb)[row * (D / 4) + lane + 32 * q];
                float a = t.x - nb.x, b = t.y - nb.y, cc = t.z - nb.z, d = t.w - nb.w;
                s += a * a + b * b + cc * cc + d * d;
            }
#pragma unroll
            for (int o = 16; o; o >>= 1) s += __shfl_xor_sync(0xffffffffu, s, o);
            if (lane == 0) g_sqnn[row * KNN + j] = s;
        }
    }
}

// ---------------- pass 2: per-warp 2-stage cp.async pipeline, no block syncs ----
#define P2T   128                 // threads/block (4 warps)
#define WPTS  64                  // points per warp (2 per lane: lane, lane+32)
#define P2P   256                 // points per block
#define DCF   16                  // floats per chunk per point
#define NCH2  (D / DCF)           // 32 chunks
#define ROWB  80                  // bytes per point row in a stage (64 + 16 pad)
#define TSTG  (WPTS * ROWB)       // 5120 B
#define NBST  (KNN * DCF * 4)     // 1280 B nb chunk
#define WSTG  (TSTG + NBST)       // 6400 B per stage
#define WBUF  (2 * WSTG)          // 12800 B per warp
#define SMEM2 (4 * WBUF)          // 51200 B per block

static __device__ __forceinline__ void cpa16(unsigned int dst, const float* src, int sz) {
    asm volatile("cp.async.cg.shared.global [%0], [%1], 16, %2;"
                 :: "r"(dst), "l"(src), "r"(sz));
}

// issue one chunk (t rows + nb chunk) into this warp's stage buffer; 1 commit group
static __device__ __forceinline__ void p2_issue(const float* __restrict__ T, int n,
                                                int wpbase, int lane,
                                                unsigned int tb, unsigned int nbb, int c) {
#pragma unroll
    for (int rr = 0; rr < 8; rr++) {
        int q  = lane + rr * 32;           // 256 granules = 64 pts x 4
        int pt = q >> 2, fc = q & 3;
        int gp = wpbase + pt;
        int sz = (gp < n) ? 16 : 0;
        const float* src = T + (size_t)(gp < n ? gp : 0) * D + c * DCF + fc * 4;
        cpa16(tb + pt * ROWB + fc * 16, src, sz);
    }
#pragma unroll
    for (int rr = 0; rr < 3; rr++) {       // 80 granules = 20 k x 4
        int g = lane + rr * 32;
        if (g < KNN * 4) {
            int k = g >> 2, piece = g & 3;
            cpa16(nbb + g * 16, g_nb + k * D + c * DCF + piece * 4, 16);
        }
    }
    asm volatile("cp.async.commit_group;");
}

__global__ __launch_bounds__(P2T, 4) void k_pass2(const float* __restrict__ T, int n) {
    extern __shared__ char sh[];
    int tid  = threadIdx.x;
    int lane = tid & 31, w = tid >> 5;
    int wpbase = blockIdx.x * P2P + w * WPTS;

    char* wbg = sh + w * WBUF;   // generic pointer to this warp's buffers
    unsigned int wb = (unsigned int)__cvta_generic_to_shared(wbg);
    unsigned int tb0 = wb,            nb0 = wb + TSTG;
    unsigned int tb1 = wb + WSTG,     nb1 = wb + WSTG + TSTG;

    p2_issue(T, n, wpbase, lane, tb0, nb0, 0);
    p2_issue(T, n, wpbase, lane, tb1, nb1, 1);

    unsigned long long a0[KNN], a1[KNN];
#pragma unroll
    for (int k = 0; k < KNN; k++) { a0[k] = 0ull; a1[k] = 0ull; }

#pragma unroll 1
    for (int c = 0; c < NCH2; c++) {
        if (c == NCH2 - 1) asm volatile("cp.async.wait_group 0;");
        else               asm volatile("cp.async.wait_group 1;");
        __syncwarp();

        const char* stage = wbg + (c & 1) * WSTG;
        const ulonglong2* t0p = (const ulonglong2*)(stage + lane * ROWB);
        const ulonglong2* t1p = (const ulonglong2*)(stage + (lane + 32) * ROWB);
        const ulonglong2* nbp = (const ulonglong2*)(stage + TSTG);
#pragma unroll
        for (int dq = 0; dq < DCF / 4; dq++) {
            ulonglong2 t0 = t0p[dq];
            ulonglong2 t1 = t1p[dq];
#pragma unroll
            for (int k = 0; k < KNN; k++) {
                ulonglong2 nb = nbp[k * 4 + dq];
                fma2(a0[k], t0.x, nb.x);
                fma2(a0[k], t0.y, nb.y);
                fma2(a1[k], t1.x, nb.x);
                fma2(a1[k], t1.y, nb.y);
            }
        }
        __syncwarp();
        if (c + 2 < NCH2) {
            unsigned int tb = (c & 1) ? tb1 : tb0;
            unsigned int nbb = (c & 1) ? nb1 : nb0;
            p2_issue(T, n, wpbase, lane, tb, nbb, c + 2);
        }
    }

    int g0 = wpbase + lane, g1 = wpbase + lane + 32;
    bool v0 = g0 < n, v1 = g1 < n;
    float tn0 = v0 ? g_tn2[g0] : 0.f;
    float tn1 = v1 ? g_tn2[g1] : 0.f;
#pragma unroll
    for (int k = 0; k < KNN; k++) {
        float2 f0 = u2f(a0[k]);
        float2 f1 = u2f(a1[k]);
        if (v0) g_sq[(size_t)k * n + g0] = tn0 - 2.f * (f0.x + f0.y);
        if (v1) g_sq[(size_t)k * n + g1] = tn1 - 2.f * (f1.x + f1.y);
    }
}

// ---------------- final scalar ----------------
__global__ void k_final(float* out) {
    int lane = threadIdx.x;
    float norm = 0.f, px = 0.f;
    if (lane < KNN) {
        float s = 0.f;
#pragma unroll
        for (int j = 0; j < KNN; j++) s += g_sqnn[lane * KNN + j];
        norm = sqrtf(s / (float)KNN);
        px = g_pxk[lane];
    }
#pragma unroll
    for (int o = 16; o; o >>= 1) {
        norm += __shfl_xor_sync(0xffffffffu, norm, o);
        px   += __shfl_xor_sync(0xffffffffu, px, o);
    }
    if (lane == 0) {
        float pdx = sqrtf(px / (float)KNN);
        float lof = pdx / norm * (float)KNN - 1.f;
        float r = erff(lof * 0.7071067811865476f);
        out[0] = fmaxf(r, 0.f);
    }
}

// ---------------- launch ----------------
extern "C" void kernel_launch(void* const* d_in, const int* in_sizes, int n_in,
                              void* d_out, int out_size) {
    const float* A = (const float*)d_in[0];
    const float* B = (const float*)d_in[1];
    const float *X, *T;
    int n;
    if (in_sizes[0] == D) { X = A; T = B; n = in_sizes[1] / D; }
    else                  { X = B; T = A; n = in_sizes[0] / D; }
    if (n > MAXN) n = MAXN;

    int nch = (n + CHUNK - 1) / CHUNK;

    cudaFuncSetAttribute(k_pass2, cudaFuncAttributeMaxDynamicSharedMemorySize, SMEM2);

    k_pass1<<<(n + 7) / 8, 256>>>(X, T, n);
    k_topk_a<<<(nch + 7) / 8, 256>>>(0, n, nch);
    k_topk_b<<<1, 256>>>(nch, 0, X, T, n);
    k_pass2<<<(n + P2P - 1) / P2P, P2T, SMEM2>>>(T, n);
    k_topk_a<<<(nch * KNN + 7) / 8, 256>>>(1, n, nch);
    k_topk_b<<<KNN, 256>>>(nch, 1, X, T, n);
    k_final<<<1, 32>>>((float*)d_out);
}